// round 5
// baseline (speedup 1.0000x reference)
#include <cuda_runtime.h>
#include <cstdint>

#define B_ 4
#define A_ 512
#define N_ 128
#define F_ 256
#define MT 64          // neighbor rows per block
#define KT 16          // K tile staged in smem
#define NTHREADS 256

// scratch for facts = x @ in2f_w + in2f_b   (B*A, F) fp32 = 2 MB
__device__ float g_facts[B_ * A_ * F_];

// ssp(v) = softplus(v) - ln2, numerically stable, fast intrinsics
__device__ __forceinline__ float sspf(float v) {
    float e = __expf(-fabsf(v));
    return fmaxf(v, 0.0f) + __logf(1.0f + e) - 0.69314718055994530942f;
}

// ============================================================
// Kernel A: facts[row, f] = sum_k x[row,k] * in2f_w[k,f] + b[f]
// ============================================================
__global__ __launch_bounds__(NTHREADS)
void facts_kernel(const float* __restrict__ x,
                  const float* __restrict__ w,
                  const float* __restrict__ bias) {
    __shared__ float xs[8 * F_];
    const int tid = threadIdx.x;
    const int r0 = blockIdx.x * 8;
    for (int idx = tid; idx < 8 * F_; idx += NTHREADS)
        xs[idx] = x[r0 * F_ + idx];
    __syncthreads();

    const int f = tid;
    float b = bias[f];
    float acc[8];
    #pragma unroll
    for (int i = 0; i < 8; i++) acc[i] = b;

    #pragma unroll 4
    for (int k = 0; k < F_; k++) {
        float wv = __ldg(w + k * F_ + f);
        #pragma unroll
        for (int i = 0; i < 8; i++)
            acc[i] = fmaf(xs[i * F_ + k], wv, acc[i]);
    }
    #pragma unroll
    for (int i = 0; i < 8; i++)
        g_facts[(r0 + i) * F_ + f] = acc[i];
}

// ============================================================
// Kernel B: fused main.
// block = (pair = b*A+a, half of N): M = 64 rows.
//   H[m,k]   = ssp(r[m]*fw1[k] + fb1[k])          (smem, 64x256)
//   W        = H @ fw2 + fb2                       (regs, 8x8/thread)
//   T[m,f]   = xi[f] * W[m,f] * xj[m,f]            (overwrite H buffer)
//   out      = ssp(T @ f2out_w + f2out_b)          (regs -> gmem float4)
// ============================================================
__global__ __launch_bounds__(NTHREADS)
void fused_kernel(const float* __restrict__ r_ij,
                  const float* __restrict__ fw1,
                  const float* __restrict__ fb1,
                  const float* __restrict__ fw2,
                  const float* __restrict__ fb2,
                  const float* __restrict__ f2w,
                  const float* __restrict__ f2b,
                  const int* __restrict__ neighbors,   // int32 (JAX x64 disabled)
                  float* __restrict__ out) {
    extern __shared__ float sm[];
    float* Hs   = sm;                    // MT*F_   (reused as T)
    float* Ws   = Hs + MT * F_;          // KT*F_   weight tile
    float* xiS  = Ws + KT * F_;          // F_
    float* fw1S = xiS + F_;              // F_
    float* fb1S = fw1S + F_;             // F_
    float* rrS  = fb1S + F_;             // MT
    int*   nbS  = (int*)(rrS + MT);      // MT   (batch-offset pre-applied)

    const int tid  = threadIdx.x;
    const int pair = blockIdx.x >> 1;
    const int half = blockIdx.x & 1;
    const int bIdx = pair / A_;          // batch index for the gather

    xiS[tid]  = g_facts[pair * F_ + tid];
    fw1S[tid] = fw1[tid];
    fb1S[tid] = fb1[tid];
    if (tid < MT) {
        rrS[tid] = r_ij[pair * N_ + half * MT + tid];
        // global facts row for neighbor j in batch bIdx
        nbS[tid] = bIdx * A_ + neighbors[pair * N_ + half * MT + tid];
    }
    __syncthreads();

    // ---- build H in smem ----
    for (int idx = tid; idx < MT * F_; idx += NTHREADS) {
        int m = idx >> 8, k = idx & (F_ - 1);
        Hs[idx] = sspf(fmaf(rrS[m], fw1S[k], fb1S[k]));
    }
    // (first __syncthreads inside GEMM loop makes H visible)

    const int warp  = tid >> 5;
    const int lane  = tid & 31;
    const int mBase = warp * 8;    // 8 warps x 8 rows = 64 rows
    const int nBase = lane * 8;    // 32 lanes x 8 cols = 256 cols

    float acc[8][8];

    // ---- GEMM1: W = H @ fw2 + fb2 ----
    {
        float b[8];
        #pragma unroll
        for (int j = 0; j < 8; j++) b[j] = fb2[nBase + j];
        #pragma unroll
        for (int i = 0; i < 8; i++)
            #pragma unroll
            for (int j = 0; j < 8; j++) acc[i][j] = b[j];
    }

    for (int kt = 0; kt < F_; kt += KT) {
        __syncthreads();   // Ws free (and H visible on first iter)
        for (int idx = tid; idx < KT * F_ / 4; idx += NTHREADS)
            ((float4*)Ws)[idx] = ((const float4*)(fw2 + kt * F_))[idx];
        __syncthreads();
        #pragma unroll
        for (int kk = 0; kk < KT; kk++) {
            float4 w0 = *(const float4*)&Ws[kk * F_ + nBase];
            float4 w1 = *(const float4*)&Ws[kk * F_ + nBase + 4];
            #pragma unroll
            for (int i = 0; i < 8; i++) {
                float a = Hs[(mBase + i) * F_ + kt + kk];   // warp broadcast
                acc[i][0] = fmaf(a, w0.x, acc[i][0]);
                acc[i][1] = fmaf(a, w0.y, acc[i][1]);
                acc[i][2] = fmaf(a, w0.z, acc[i][2]);
                acc[i][3] = fmaf(a, w0.w, acc[i][3]);
                acc[i][4] = fmaf(a, w1.x, acc[i][4]);
                acc[i][5] = fmaf(a, w1.y, acc[i][5]);
                acc[i][6] = fmaf(a, w1.z, acc[i][6]);
                acc[i][7] = fmaf(a, w1.w, acc[i][7]);
            }
        }
    }
    __syncthreads();   // all H reads complete before overwrite

    // ---- elementwise: T = xi * W * xj, write into Hs buffer ----
    {
        float xi[8];
        #pragma unroll
        for (int j = 0; j < 8; j++) xi[j] = xiS[nBase + j];

        #pragma unroll
        for (int i = 0; i < 8; i++) {
            int m = mBase + i;
            const float4* xjp = (const float4*)(g_facts + (size_t)nbS[m] * F_ + nBase);
            float4 xj0 = xjp[0];
            float4 xj1 = xjp[1];
            float4 t0, t1;
            t0.x = xi[0] * acc[i][0] * xj0.x;
            t0.y = xi[1] * acc[i][1] * xj0.y;
            t0.z = xi[2] * acc[i][2] * xj0.z;
            t0.w = xi[3] * acc[i][3] * xj0.w;
            t1.x = xi[4] * acc[i][4] * xj1.x;
            t1.y = xi[5] * acc[i][5] * xj1.y;
            t1.z = xi[6] * acc[i][6] * xj1.z;
            t1.w = xi[7] * acc[i][7] * xj1.w;
            *(float4*)&Hs[m * F_ + nBase]     = t0;
            *(float4*)&Hs[m * F_ + nBase + 4] = t1;
        }
    }

    // ---- GEMM2: out = T @ f2out_w + f2out_b ----
    {
        float b[8];
        #pragma unroll
        for (int j = 0; j < 8; j++) b[j] = f2b[nBase + j];
        #pragma unroll
        for (int i = 0; i < 8; i++)
            #pragma unroll
            for (int j = 0; j < 8; j++) acc[i][j] = b[j];
    }

    for (int kt = 0; kt < F_; kt += KT) {
        __syncthreads();   // Ws free; T writes visible on first iter
        for (int idx = tid; idx < KT * F_ / 4; idx += NTHREADS)
            ((float4*)Ws)[idx] = ((const float4*)(f2w + kt * F_))[idx];
        __syncthreads();
        #pragma unroll
        for (int kk = 0; kk < KT; kk++) {
            float4 w0 = *(const float4*)&Ws[kk * F_ + nBase];
            float4 w1 = *(const float4*)&Ws[kk * F_ + nBase + 4];
            #pragma unroll
            for (int i = 0; i < 8; i++) {
                float a = Hs[(mBase + i) * F_ + kt + kk];
                acc[i][0] = fmaf(a, w0.x, acc[i][0]);
                acc[i][1] = fmaf(a, w0.y, acc[i][1]);
                acc[i][2] = fmaf(a, w0.z, acc[i][2]);
                acc[i][3] = fmaf(a, w0.w, acc[i][3]);
                acc[i][4] = fmaf(a, w1.x, acc[i][4]);
                acc[i][5] = fmaf(a, w1.y, acc[i][5]);
                acc[i][6] = fmaf(a, w1.z, acc[i][6]);
                acc[i][7] = fmaf(a, w1.w, acc[i][7]);
            }
        }
    }

    // ---- epilogue: ssp + store ----
    const int rowBase = (pair * N_ + half * MT + mBase) * F_ + nBase;
    #pragma unroll
    for (int i = 0; i < 8; i++) {
        float4 v0, v1;
        v0.x = sspf(acc[i][0]); v0.y = sspf(acc[i][1]);
        v0.z = sspf(acc[i][2]); v0.w = sspf(acc[i][3]);
        v1.x = sspf(acc[i][4]); v1.y = sspf(acc[i][5]);
        v1.z = sspf(acc[i][6]); v1.w = sspf(acc[i][7]);
        *(float4*)&out[rowBase + i * F_]     = v0;
        *(float4*)&out[rowBase + i * F_ + 4] = v1;
    }
}

// smem: Hs + Ws + xi + fw1 + fb1 + rr (floats) + nb (ints)
static const int SMEM_BYTES =
    (MT * F_ + KT * F_ + 3 * F_ + MT) * (int)sizeof(float) + MT * (int)sizeof(int);

extern "C" void kernel_launch(void* const* d_in, const int* in_sizes, int n_in,
                              void* d_out, int out_size) {
    const float* x        = (const float*)d_in[0];
    const float* r_ij     = (const float*)d_in[1];
    // d_in[2] pairwise_mask: unused by reference (all-ones, and never applied)
    const float* in2f_w   = (const float*)d_in[3];
    const float* in2f_b   = (const float*)d_in[4];
    const float* f2out_w  = (const float*)d_in[5];
    const float* f2out_b  = (const float*)d_in[6];
    const float* fw1      = (const float*)d_in[7];
    const float* fb1      = (const float*)d_in[8];
    const float* fw2      = (const float*)d_in[9];
    const float* fb2      = (const float*)d_in[10];
    const int*   neighbors= (const int*)d_in[11];   // int32!
    float*       out      = (float*)d_out;

    cudaFuncSetAttribute(fused_kernel,
                         cudaFuncAttributeMaxDynamicSharedMemorySize, SMEM_BYTES);

    facts_kernel<<<(B_ * A_) / 8, NTHREADS>>>(x, in2f_w, in2f_b);
    fused_kernel<<<B_ * A_ * 2, NTHREADS, SMEM_BYTES>>>(
        r_ij, fw1, fb1, fw2, fb2, f2out_w, f2out_b, neighbors, out);
}

// round 6
// speedup vs baseline: 1.2452x; 1.2452x over previous
#include <cuda_runtime.h>
#include <cstdint>

#define B_ 4
#define A_ 512
#define N_ 128
#define F_ 256
#define MT 64          // neighbor rows per block
#define KT 16          // K tile staged in smem
#define NTHREADS 256

// scratch for facts = x @ in2f_w + in2f_b   (B*A, F) fp32 = 2 MB
__device__ float g_facts[B_ * A_ * F_];

// ssp(v) = softplus(v) - ln2, numerically stable, fast intrinsics
__device__ __forceinline__ float sspf(float v) {
    float e = __expf(-fabsf(v));
    return fmaxf(v, 0.0f) + __logf(1.0f + e) - 0.69314718055994530942f;
}

// ---- packed f32x2 helpers (Blackwell FFMA2 path) ----
__device__ __forceinline__ unsigned long long pack2(float x, float y) {
    unsigned long long r;
    asm("mov.b64 %0, {%1, %2};" : "=l"(r) : "f"(x), "f"(y));
    return r;
}
__device__ __forceinline__ void unpack2(unsigned long long v, float& x, float& y) {
    asm("mov.b64 {%0, %1}, %2;" : "=f"(x), "=f"(y) : "l"(v));
}
__device__ __forceinline__ void ffma2(unsigned long long& d,
                                      unsigned long long a,
                                      unsigned long long b) {
    asm("fma.rn.f32x2 %0, %1, %2, %0;" : "+l"(d) : "l"(a), "l"(b));
}

// ============================================================
// Kernel A: facts[row, f] = sum_k x[row,k] * in2f_w[k,f] + b[f]
// ============================================================
__global__ __launch_bounds__(NTHREADS)
void facts_kernel(const float* __restrict__ x,
                  const float* __restrict__ w,
                  const float* __restrict__ bias) {
    __shared__ float xs[8 * F_];
    const int tid = threadIdx.x;
    const int r0 = blockIdx.x * 8;
    for (int idx = tid; idx < 8 * F_; idx += NTHREADS)
        xs[idx] = x[r0 * F_ + idx];
    __syncthreads();

    const int f = tid;
    float b = bias[f];
    float acc[8];
    #pragma unroll
    for (int i = 0; i < 8; i++) acc[i] = b;

    #pragma unroll 4
    for (int k = 0; k < F_; k++) {
        float wv = __ldg(w + k * F_ + f);
        #pragma unroll
        for (int i = 0; i < 8; i++)
            acc[i] = fmaf(xs[i * F_ + k], wv, acc[i]);
    }
    #pragma unroll
    for (int i = 0; i < 8; i++)
        g_facts[(r0 + i) * F_ + f] = acc[i];
}

// ============================================================
// Double-buffered smem-tiled GEMM step: acc += Hs[64xF] @ gW[FxF]
// Thread tile: 8 rows (mBase..+7) x 8 cols ({cb0..+3} U {cb1..+3}).
// W loaded as packed ulonglong2 (conflict-free LDS.128),
// A loaded as float4 warp-broadcast over 4 consecutive k.
// ============================================================
__device__ __forceinline__ void tile_gemm(const float* __restrict__ gW,
                                          const float* __restrict__ Hs,
                                          float* __restrict__ Ws0,
                                          float* __restrict__ Ws1,
                                          int mBase, int cb0, int cb1, int tid,
                                          unsigned long long acc[8][4]) {
    const int NT = F_ / KT;  // 16 tiles
    // prologue: stage tile 0
    #pragma unroll
    for (int j = 0; j < KT * F_ / 4 / NTHREADS; j++)
        ((float4*)Ws0)[tid + j * NTHREADS] = ((const float4*)gW)[tid + j * NTHREADS];
    __syncthreads();   // tile0 visible; also orders prior Hs writes

    for (int t = 0; t < NT; t++) {
        const float* Wb = (t & 1) ? Ws1 : Ws0;
        float*       Wn = (t & 1) ? Ws0 : Ws1;
        const int kt = t * KT;

        // prefetch next tile gmem -> regs
        float4 pf[KT * F_ / 4 / NTHREADS];
        if (t + 1 < NT) {
            #pragma unroll
            for (int j = 0; j < KT * F_ / 4 / NTHREADS; j++)
                pf[j] = ((const float4*)(gW + (t + 1) * KT * F_))[tid + j * NTHREADS];
        }

        #pragma unroll
        for (int kk4 = 0; kk4 < KT; kk4 += 4) {
            unsigned long long w[4][4];
            #pragma unroll
            for (int kk = 0; kk < 4; kk++) {
                const float* wr = Wb + (kk4 + kk) * F_;
                ulonglong2 g0 = *(const ulonglong2*)(wr + cb0);
                ulonglong2 g1 = *(const ulonglong2*)(wr + cb1);
                w[kk][0] = g0.x; w[kk][1] = g0.y;
                w[kk][2] = g1.x; w[kk][3] = g1.y;
            }
            #pragma unroll
            for (int i = 0; i < 8; i++) {
                float4 a = *(const float4*)&Hs[(mBase + i) * F_ + kt + kk4]; // broadcast
                unsigned long long ap;
                ap = pack2(a.x, a.x);
                ffma2(acc[i][0], ap, w[0][0]); ffma2(acc[i][1], ap, w[0][1]);
                ffma2(acc[i][2], ap, w[0][2]); ffma2(acc[i][3], ap, w[0][3]);
                ap = pack2(a.y, a.y);
                ffma2(acc[i][0], ap, w[1][0]); ffma2(acc[i][1], ap, w[1][1]);
                ffma2(acc[i][2], ap, w[1][2]); ffma2(acc[i][3], ap, w[1][3]);
                ap = pack2(a.z, a.z);
                ffma2(acc[i][0], ap, w[2][0]); ffma2(acc[i][1], ap, w[2][1]);
                ffma2(acc[i][2], ap, w[2][2]); ffma2(acc[i][3], ap, w[2][3]);
                ap = pack2(a.w, a.w);
                ffma2(acc[i][0], ap, w[3][0]); ffma2(acc[i][1], ap, w[3][1]);
                ffma2(acc[i][2], ap, w[3][2]); ffma2(acc[i][3], ap, w[3][3]);
            }
        }

        if (t + 1 < NT) {
            #pragma unroll
            for (int j = 0; j < KT * F_ / 4 / NTHREADS; j++)
                ((float4*)Wn)[tid + j * NTHREADS] = pf[j];
        }
        __syncthreads();
    }
}

// ============================================================
// Kernel B: fused main.  block = (pair, half of N): 64 rows.
// ============================================================
__global__ __launch_bounds__(NTHREADS, 2)
void fused_kernel(const float* __restrict__ r_ij,
                  const float* __restrict__ fw1,
                  const float* __restrict__ fb1,
                  const float* __restrict__ fw2,
                  const float* __restrict__ fb2,
                  const float* __restrict__ f2w,
                  const float* __restrict__ f2b,
                  const int* __restrict__ neighbors,   // int32
                  float* __restrict__ out) {
    extern __shared__ float sm[];
    float* Hs   = sm;                    // MT*F_   (reused as T)
    float* Ws0  = Hs  + MT * F_;         // KT*F_
    float* Ws1  = Ws0 + KT * F_;         // KT*F_
    float* xiS  = Ws1 + KT * F_;         // F_
    float* fw1S = xiS + F_;              // F_
    float* fb1S = fw1S + F_;             // F_
    float* rrS  = fb1S + F_;             // MT
    int*   nbS  = (int*)(rrS + MT);      // MT

    const int tid  = threadIdx.x;
    const int pair = blockIdx.x >> 1;
    const int half = blockIdx.x & 1;
    const int bIdx = pair / A_;

    xiS[tid]  = g_facts[pair * F_ + tid];
    fw1S[tid] = fw1[tid];
    fb1S[tid] = fb1[tid];
    if (tid < MT) {
        rrS[tid] = r_ij[pair * N_ + half * MT + tid];
        nbS[tid] = bIdx * A_ + neighbors[pair * N_ + half * MT + tid];
    }
    __syncthreads();

    // ---- build H in smem ----
    for (int idx = tid; idx < MT * F_; idx += NTHREADS) {
        int m = idx >> 8, k = idx & (F_ - 1);
        Hs[idx] = sspf(fmaf(rrS[m], fw1S[k], fb1S[k]));
    }
    // (visibility handled by tile_gemm's prologue sync)

    const int warp  = tid >> 5;
    const int lane  = tid & 31;
    const int mBase = warp * 8;        // 8 warps x 8 rows
    const int cb0   = lane * 4;        // cols [lane*4, +4)
    const int cb1   = 128 + lane * 4;  // cols [128+lane*4, +4)

    unsigned long long acc[8][4];

    // ---- GEMM1: W = H @ fw2 + fb2 ----
    {
        float4 b0 = *(const float4*)&fb2[cb0];
        float4 b1 = *(const float4*)&fb2[cb1];
        unsigned long long p0 = pack2(b0.x, b0.y), p1 = pack2(b0.z, b0.w);
        unsigned long long p2 = pack2(b1.x, b1.y), p3 = pack2(b1.z, b1.w);
        #pragma unroll
        for (int i = 0; i < 8; i++) {
            acc[i][0] = p0; acc[i][1] = p1; acc[i][2] = p2; acc[i][3] = p3;
        }
    }
    tile_gemm(fw2, Hs, Ws0, Ws1, mBase, cb0, cb1, tid, acc);

    __syncthreads();   // all Hs reads done before overwrite with T

    // ---- elementwise: T = xi * W * xj -> Hs ----
    {
        float4 xi0 = *(const float4*)&xiS[cb0];
        float4 xi1 = *(const float4*)&xiS[cb1];
        #pragma unroll
        for (int i = 0; i < 8; i++) {
            int m = mBase + i;
            const float* xjr = g_facts + (size_t)nbS[m] * F_;
            float4 xj0 = *(const float4*)(xjr + cb0);
            float4 xj1 = *(const float4*)(xjr + cb1);
            float w0, w1, w2, w3, w4, w5, w6, w7;
            unpack2(acc[i][0], w0, w1);
            unpack2(acc[i][1], w2, w3);
            unpack2(acc[i][2], w4, w5);
            unpack2(acc[i][3], w6, w7);
            float4 t0, t1;
            t0.x = xi0.x * w0 * xj0.x;  t0.y = xi0.y * w1 * xj0.y;
            t0.z = xi0.z * w2 * xj0.z;  t0.w = xi0.w * w3 * xj0.w;
            t1.x = xi1.x * w4 * xj1.x;  t1.y = xi1.y * w5 * xj1.y;
            t1.z = xi1.z * w6 * xj1.z;  t1.w = xi1.w * w7 * xj1.w;
            *(float4*)&Hs[m * F_ + cb0] = t0;
            *(float4*)&Hs[m * F_ + cb1] = t1;
        }
    }
    // (T visibility handled by tile_gemm's prologue sync)

    // ---- GEMM2: out = ssp(T @ f2out_w + f2out_b) ----
    {
        float4 b0 = *(const float4*)&f2b[cb0];
        float4 b1 = *(const float4*)&f2b[cb1];
        unsigned long long p0 = pack2(b0.x, b0.y), p1 = pack2(b0.z, b0.w);
        unsigned long long p2 = pack2(b1.x, b1.y), p3 = pack2(b1.z, b1.w);
        #pragma unroll
        for (int i = 0; i < 8; i++) {
            acc[i][0] = p0; acc[i][1] = p1; acc[i][2] = p2; acc[i][3] = p3;
        }
    }
    tile_gemm(f2w, Hs, Ws0, Ws1, mBase, cb0, cb1, tid, acc);

    // ---- epilogue ----
    const int rowBase = (pair * N_ + half * MT + mBase) * F_;
    #pragma unroll
    for (int i = 0; i < 8; i++) {
        float o0, o1, o2, o3, o4, o5, o6, o7;
        unpack2(acc[i][0], o0, o1);
        unpack2(acc[i][1], o2, o3);
        unpack2(acc[i][2], o4, o5);
        unpack2(acc[i][3], o6, o7);
        float4 v0, v1;
        v0.x = sspf(o0); v0.y = sspf(o1); v0.z = sspf(o2); v0.w = sspf(o3);
        v1.x = sspf(o4); v1.y = sspf(o5); v1.z = sspf(o6); v1.w = sspf(o7);
        *(float4*)&out[rowBase + i * F_ + cb0] = v0;
        *(float4*)&out[rowBase + i * F_ + cb1] = v1;
    }
}

// smem: Hs + 2*Ws + xi + fw1 + fb1 + rr + nb
static const int SMEM_BYTES =
    (MT * F_ + 2 * KT * F_ + 3 * F_ + MT) * (int)sizeof(float) + MT * (int)sizeof(int);

extern "C" void kernel_launch(void* const* d_in, const int* in_sizes, int n_in,
                              void* d_out, int out_size) {
    const float* x        = (const float*)d_in[0];
    const float* r_ij     = (const float*)d_in[1];
    // d_in[2] pairwise_mask: unused by reference
    const float* in2f_w   = (const float*)d_in[3];
    const float* in2f_b   = (const float*)d_in[4];
    const float* f2out_w  = (const float*)d_in[5];
    const float* f2out_b  = (const float*)d_in[6];
    const float* fw1      = (const float*)d_in[7];
    const float* fb1      = (const float*)d_in[8];
    const float* fw2      = (const float*)d_in[9];
    const float* fb2      = (const float*)d_in[10];
    const int*   neighbors= (const int*)d_in[11];
    float*       out      = (float*)d_out;

    cudaFuncSetAttribute(fused_kernel,
                         cudaFuncAttributeMaxDynamicSharedMemorySize, SMEM_BYTES);

    facts_kernel<<<(B_ * A_) / 8, NTHREADS>>>(x, in2f_w, in2f_b);
    fused_kernel<<<B_ * A_ * 2, NTHREADS, SMEM_BYTES>>>(
        r_ij, fw1, fb1, fw2, fb2, f2out_w, f2out_b, neighbors, out);
}

// round 10
// speedup vs baseline: 1.6410x; 1.3178x over previous
#include <cuda_runtime.h>
#include <cuda_bf16.h>
#include <cstdint>

#define B_ 4
#define A_ 512
#define N_ 128
#define F_ 256
#define NTH 256
#define NSL 8                      // K slices of 32
#define RS 80                      // padded smem row stride (bytes)
#define TILE_BYTES (128 * RS)      // one 128-row bf16 tile (hi OR lo)
#define BUF_BYTES  (2 * TILE_BYTES)
#define SM_A   0
#define SM_B   (2 * BUF_BYTES)     // 40960
#define SM_XI   81920
#define SM_BIAS 82944
#define SM_RR   83968
#define SM_NB   84480
#define SM_FW1  84992
#define SM_FB1  86016
#define SMEM_TOTAL 87040

// ---------------- device scratch ----------------
__device__ float g_facts[B_ * A_ * F_];                        // 2 MB
__device__ __nv_bfloat16 g_w1T_hi[F_ * F_], g_w1T_lo[F_ * F_]; // fw2^T split
__device__ __nv_bfloat16 g_w2T_hi[F_ * F_], g_w2T_lo[F_ * F_]; // f2out_w^T split
__device__ __nv_bfloat16 g_T_hi[(size_t)B_ * A_ * N_ * F_];    // 128 MB
__device__ __nv_bfloat16 g_T_lo[(size_t)B_ * A_ * N_ * F_];    // 128 MB

// ---------------- helpers ----------------
__device__ __forceinline__ float sspf(float v) {
    float e = __expf(-fabsf(v));
    return fmaxf(v, 0.0f) + __logf(1.0f + e) - 0.69314718055994530942f;
}
__device__ __forceinline__ uint32_t smem_u32(const void* p) {
    uint32_t a;
    asm("{ .reg .u64 t; cvta.to.shared.u64 t, %1; cvt.u32.u64 %0, t; }" : "=r"(a) : "l"(p));
    return a;
}
// split two floats into packed bf16x2 hi and lo words
__device__ __forceinline__ void split2(float x, float y, uint32_t& hi, uint32_t& lo) {
    __nv_bfloat16 hx = __float2bfloat16(x);
    __nv_bfloat16 hy = __float2bfloat16(y);
    __nv_bfloat16 lx = __float2bfloat16(x - __bfloat162float(hx));
    __nv_bfloat16 ly = __float2bfloat16(y - __bfloat162float(hy));
    hi = (uint32_t)__bfloat16_as_ushort(hx) | ((uint32_t)__bfloat16_as_ushort(hy) << 16);
    lo = (uint32_t)__bfloat16_as_ushort(lx) | ((uint32_t)__bfloat16_as_ushort(ly) << 16);
}
__device__ __forceinline__ void ldsm4(uint32_t* r, uint32_t addr) {
    asm volatile("ldmatrix.sync.aligned.m8n8.x4.shared.b16 {%0,%1,%2,%3}, [%4];"
                 : "=r"(r[0]), "=r"(r[1]), "=r"(r[2]), "=r"(r[3]) : "r"(addr));
}
__device__ __forceinline__ void mma16816(float* c, const uint32_t* a,
                                         uint32_t b0, uint32_t b1) {
    asm volatile("mma.sync.aligned.m16n8k16.row.col.f32.bf16.bf16.f32 "
                 "{%0,%1,%2,%3}, {%4,%5,%6,%7}, {%8,%9}, {%0,%1,%2,%3};"
                 : "+f"(c[0]), "+f"(c[1]), "+f"(c[2]), "+f"(c[3])
                 : "r"(a[0]), "r"(a[1]), "r"(a[2]), "r"(a[3]), "r"(b0), "r"(b1));
}
__device__ __forceinline__ void cp16(uint32_t dst, const void* src) {
    asm volatile("cp.async.cg.shared.global [%0], [%1], 16;" :: "r"(dst), "l"(src));
}
#define CP_COMMIT() asm volatile("cp.async.commit_group;" ::: "memory")
#define CP_WAIT1()  asm volatile("cp.async.wait_group 1;" ::: "memory")
#define CP_WAIT0()  asm volatile("cp.async.wait_group 0;" ::: "memory")

// one K-slice of MMA work: acc += A(buf) @ B(buf)^T, 3-product bf16 split
__device__ __forceinline__ void mma_slice(uint32_t sb, int buf, int warpM, int warpN,
                                          int lane, float acc[2][8][4]) {
    const uint32_t aBase = sb + SM_A + buf * BUF_BYTES
        + (warpM * 32 + (lane & 15)) * RS + ((lane >> 4) * 16);
    const uint32_t bBase = sb + SM_B + buf * BUF_BYTES
        + (warpN * 64 + (lane & 7) + ((lane >> 4) & 1) * 8) * RS
        + (((lane >> 3) & 1) * 16);
    #pragma unroll
    for (int kt = 0; kt < 2; kt++) {
        uint32_t Ah0[4], Ah1[4], Al0[4], Al1[4];
        ldsm4(Ah0, aBase + kt * 32);
        ldsm4(Ah1, aBase + 16 * RS + kt * 32);
        ldsm4(Al0, aBase + TILE_BYTES + kt * 32);
        ldsm4(Al1, aBase + TILE_BYTES + 16 * RS + kt * 32);
        #pragma unroll
        for (int nc = 0; nc < 4; nc++) {
            uint32_t Bh[4], Bl[4];
            ldsm4(Bh, bBase + nc * 16 * RS + kt * 32);
            ldsm4(Bl, bBase + TILE_BYTES + nc * 16 * RS + kt * 32);
            #pragma unroll
            for (int ns = 0; ns < 2; ns++) {
                int n8 = nc * 2 + ns;
                mma16816(acc[0][n8], Ah0, Bh[2 * ns], Bh[2 * ns + 1]);
                mma16816(acc[0][n8], Al0, Bh[2 * ns], Bh[2 * ns + 1]);
                mma16816(acc[0][n8], Ah0, Bl[2 * ns], Bl[2 * ns + 1]);
                mma16816(acc[1][n8], Ah1, Bh[2 * ns], Bh[2 * ns + 1]);
                mma16816(acc[1][n8], Al1, Bh[2 * ns], Bh[2 * ns + 1]);
                mma16816(acc[1][n8], Ah1, Bl[2 * ns], Bl[2 * ns + 1]);
            }
        }
    }
}

// issue cp.async of one B slice (weights, transposed bf16 hi/lo) into buf
__device__ __forceinline__ void issueB(uint32_t sb, int buf, int s, int nh, int tid,
                                       const __nv_bfloat16* gHi,
                                       const __nv_bfloat16* gLo) {
    #pragma unroll
    for (int i = 0; i < 4; i++) {
        int o = tid + i * NTH;
        int r = o >> 2, j = o & 3;
        int sel = r >> 7, n = r & 127;
        const __nv_bfloat16* src =
            (sel ? gLo : gHi) + (size_t)(nh * 128 + n) * F_ + s * 32 + j * 8;
        cp16(sb + SM_B + buf * BUF_BYTES + sel * TILE_BYTES + n * RS + j * 16, src);
    }
}

// ============================================================
// K1: facts = x @ in2f_w + in2f_b
// ============================================================
__global__ __launch_bounds__(NTH)
void facts_kernel(const float* __restrict__ x, const float* __restrict__ w,
                  const float* __restrict__ bias) {
    __shared__ float xs[8 * F_];
    const int tid = threadIdx.x;
    const int r0 = blockIdx.x * 8;
    for (int idx = tid; idx < 8 * F_; idx += NTH) xs[idx] = x[r0 * F_ + idx];
    __syncthreads();
    float b = bias[tid];
    float acc[8];
    #pragma unroll
    for (int i = 0; i < 8; i++) acc[i] = b;
    #pragma unroll 4
    for (int k = 0; k < F_; k++) {
        float wv = __ldg(w + k * F_ + tid);
        #pragma unroll
        for (int i = 0; i < 8; i++) acc[i] = fmaf(xs[i * F_ + k], wv, acc[i]);
    }
    #pragma unroll
    for (int i = 0; i < 8; i++) g_facts[(r0 + i) * F_ + tid] = acc[i];
}

// ============================================================
// K0: transpose + bf16 hi/lo split of the two weight matrices
// ============================================================
__global__ void split_kernel(const float* __restrict__ fw2,
                             const float* __restrict__ f2w) {
    int n = blockIdx.x, k = threadIdx.x, s = blockIdx.y;
    float v = (s ? f2w : fw2)[k * F_ + n];
    __nv_bfloat16 hi = __float2bfloat16(v);
    __nv_bfloat16 lo = __float2bfloat16(v - __bfloat162float(hi));
    if (s) { g_w2T_hi[n * F_ + k] = hi; g_w2T_lo[n * F_ + k] = lo; }
    else   { g_w1T_hi[n * F_ + k] = hi; g_w1T_lo[n * F_ + k] = lo; }
}

// ============================================================
// K2: GEMM1 (W = H @ fw2) + fused T = xi*(W+fb2)*xj -> g_T (bf16 split)
// block = (pair, n-half): out tile 128 x 128
// ============================================================
__global__ __launch_bounds__(NTH, 1)
void gemm1_kernel(const float* __restrict__ r_ij, const float* __restrict__ fw1,
                  const float* __restrict__ fb1, const float* __restrict__ fb2,
                  const int* __restrict__ neighbors) {
    extern __shared__ __align__(16) char smem[];
    const uint32_t sb = smem_u32(smem);
    const int tid = threadIdx.x, wid = tid >> 5, lane = tid & 31;
    const int warpM = wid & 3, warpN = wid >> 2;
    const int pair = blockIdx.x >> 1, nh = blockIdx.x & 1;
    const int bIdx = pair / A_;

    float* xiS   = (float*)(smem + SM_XI);
    float* biasS = (float*)(smem + SM_BIAS);
    float* rrS   = (float*)(smem + SM_RR);
    int*   nbS   = (int*)(smem + SM_NB);
    float* fw1S  = (float*)(smem + SM_FW1);
    float* fb1S  = (float*)(smem + SM_FB1);

    xiS[tid]   = g_facts[pair * F_ + tid];
    biasS[tid] = fb2[tid];
    fw1S[tid]  = fw1[tid];
    fb1S[tid]  = fb1[tid];
    if (tid < N_) {
        rrS[tid] = r_ij[pair * N_ + tid];
        nbS[tid] = bIdx * A_ + neighbors[pair * N_ + tid];
    }
    __syncthreads();

    // build H slice (128 x 32) as bf16 hi/lo into A buf
    auto buildH = [&](int s, int buf) {
        int m = tid >> 1, h0 = (tid & 1) * 16;
        float rr = rrS[m];
        char* base = smem + SM_A + buf * BUF_BYTES + m * RS;
        #pragma unroll
        for (int j = 0; j < 16; j += 2) {
            int k = s * 32 + h0 + j;
            float v0 = sspf(fmaf(rr, fw1S[k],     fb1S[k]));
            float v1 = sspf(fmaf(rr, fw1S[k + 1], fb1S[k + 1]));
            uint32_t hi, lo;
            split2(v0, v1, hi, lo);
            *(uint32_t*)(base + (h0 + j) * 2)              = hi;
            *(uint32_t*)(base + TILE_BYTES + (h0 + j) * 2) = lo;
        }
    };

    float acc[2][8][4];
    #pragma unroll
    for (int i = 0; i < 2; i++)
        #pragma unroll
        for (int j = 0; j < 8; j++)
            #pragma unroll
            for (int q = 0; q < 4; q++) acc[i][j][q] = 0.0f;

    buildH(0, 0);
    issueB(sb, 0, 0, nh, tid, g_w1T_hi, g_w1T_lo);
    CP_COMMIT();

    for (int s = 0; s < NSL; s++) {
        if (s + 1 < NSL) {
            buildH(s + 1, (s + 1) & 1);
            issueB(sb, (s + 1) & 1, s + 1, nh, tid, g_w1T_hi, g_w1T_lo);
            CP_COMMIT();
            CP_WAIT1();
        } else {
            CP_WAIT0();
        }
        __syncthreads();
        mma_slice(sb, s & 1, warpM, warpN, lane, acc);
        __syncthreads();
    }

    // epilogue: T = xi * (acc + fb2) * xj  -> bf16 split -> g_T
    const int r0 = lane >> 2, c0 = (lane & 3) * 2;
    #pragma unroll
    for (int mt = 0; mt < 2; mt++) {
        #pragma unroll
        for (int n8 = 0; n8 < 8; n8++) {
            int colG = nh * 128 + warpN * 64 + n8 * 8 + c0;
            float xi0 = xiS[colG], xi1 = xiS[colG + 1];
            float b0 = biasS[colG], b1 = biasS[colG + 1];
            #pragma unroll
            for (int rh = 0; rh < 2; rh++) {
                int rowL = warpM * 32 + mt * 16 + r0 + rh * 8;
                size_t gRow = (size_t)pair * N_ + rowL;
                const float2 xj = *(const float2*)(g_facts + (size_t)nbS[rowL] * F_ + colG);
                float t0 = xi0 * (acc[mt][n8][rh * 2 + 0] + b0) * xj.x;
                float t1 = xi1 * (acc[mt][n8][rh * 2 + 1] + b1) * xj.y;
                uint32_t hi, lo;
                split2(t0, t1, hi, lo);
                *(uint32_t*)&g_T_hi[gRow * F_ + colG] = hi;
                *(uint32_t*)&g_T_lo[gRow * F_ + colG] = lo;
            }
        }
    }
}

// ============================================================
// K3: GEMM2: out = ssp(T @ f2out_w + f2out_b)
// ============================================================
__global__ __launch_bounds__(NTH, 1)
void gemm2_kernel(const float* __restrict__ f2b, float* __restrict__ out) {
    extern __shared__ __align__(16) char smem[];
    const uint32_t sb = smem_u32(smem);
    const int tid = threadIdx.x, wid = tid >> 5, lane = tid & 31;
    const int warpM = wid & 3, warpN = wid >> 2;
    const int pair = blockIdx.x >> 1, nh = blockIdx.x & 1;

    float* biasS = (float*)(smem + SM_BIAS);
    biasS[tid] = f2b[tid];
    __syncthreads();

    auto issueA = [&](int s, int buf) {
        #pragma unroll
        for (int i = 0; i < 4; i++) {
            int o = tid + i * NTH;
            int r = o >> 2, j = o & 3;
            int sel = r >> 7, m = r & 127;
            const __nv_bfloat16* src =
                (sel ? g_T_lo : g_T_hi) + ((size_t)pair * N_ + m) * F_ + s * 32 + j * 8;
            cp16(sb + SM_A + buf * BUF_BYTES + sel * TILE_BYTES + m * RS + j * 16, src);
        }
    };

    float acc[2][8][4];
    #pragma unroll
    for (int i = 0; i < 2; i++)
        #pragma unroll
        for (int j = 0; j < 8; j++)
            #pragma unroll
            for (int q = 0; q < 4; q++) acc[i][j][q] = 0.0f;

    issueA(0, 0);
    issueB(sb, 0, 0, nh, tid, g_w2T_hi, g_w2T_lo);
    CP_COMMIT();

    for (int s = 0; s < NSL; s++) {
        if (s + 1 < NSL) {
            issueA(s + 1, (s + 1) & 1);
            issueB(sb, (s + 1) & 1, s + 1, nh, tid, g_w2T_hi, g_w2T_lo);
            CP_COMMIT();
            CP_WAIT1();
        } else {
            CP_WAIT0();
        }
        __syncthreads();
        mma_slice(sb, s & 1, warpM, warpN, lane, acc);
        __syncthreads();
    }

    const int r0 = lane >> 2, c0 = (lane & 3) * 2;
    #pragma unroll
    for (int mt = 0; mt < 2; mt++) {
        #pragma unroll
        for (int n8 = 0; n8 < 8; n8++) {
            int colG = nh * 128 + warpN * 64 + n8 * 8 + c0;
            float b0 = biasS[colG], b1 = biasS[colG + 1];
            #pragma unroll
            for (int rh = 0; rh < 2; rh++) {
                int rowL = warpM * 32 + mt * 16 + r0 + rh * 8;
                size_t gRow = (size_t)pair * N_ + rowL;
                float2 v;
                v.x = sspf(acc[mt][n8][rh * 2 + 0] + b0);
                v.y = sspf(acc[mt][n8][rh * 2 + 1] + b1);
                *(float2*)(out + gRow * F_ + colG) = v;
            }
        }
    }
}

extern "C" void kernel_launch(void* const* d_in, const int* in_sizes, int n_in,
                              void* d_out, int out_size) {
    const float* x        = (const float*)d_in[0];
    const float* r_ij     = (const float*)d_in[1];
    // d_in[2] pairwise_mask: unused by reference
    const float* in2f_w   = (const float*)d_in[3];
    const float* in2f_b   = (const float*)d_in[4];
    const float* f2out_w  = (const float*)d_in[5];
    const float* f2out_b  = (const float*)d_in[6];
    const float* fw1      = (const float*)d_in[7];
    const float* fb1      = (const float*)d_in[8];
    const float* fw2      = (const float*)d_in[9];
    const float* fb2      = (const float*)d_in[10];
    const int*   neighbors= (const int*)d_in[11];
    float*       out      = (float*)d_out;

    cudaFuncSetAttribute(gemm1_kernel,
                         cudaFuncAttributeMaxDynamicSharedMemorySize, SMEM_TOTAL);
    cudaFuncSetAttribute(gemm2_kernel,
                         cudaFuncAttributeMaxDynamicSharedMemorySize, SMEM_TOTAL);

    split_kernel<<<dim3(F_, 2), F_>>>(fw2, f2out_w);
    facts_kernel<<<(B_ * A_) / 8, NTH>>>(x, in2f_w, in2f_b);
    gemm1_kernel<<<B_ * A_ * 2, NTH, SMEM_TOTAL>>>(r_ij, fw1, fb1, fb2, neighbors);
    gemm2_kernel<<<B_ * A_ * 2, NTH, SMEM_TOTAL>>>(f2out_b, out);
}